// round 1
// baseline (speedup 1.0000x reference)
#include <cuda_runtime.h>
#include <cstdint>

// ---------------- scratch (device globals: allocation-free) ----------------
__device__ float g_patches[64 * 256 * 256];     // [16384, 256] im2col
__device__ float g_wt[256 * 1024];              // conv_w transposed [256, 1024]
__device__ float g_tok[16384 * 1024];           // tokens [B*T, C]
__device__ float g_q[16384 * 1024];             // q in [B,H,T,D]
__device__ float g_y[16384 * 1024];             // attn out in [B,T,C]

// ---------------- packed f32x2 helpers (FFMA2: PTX-only on sm_103a) --------
__device__ __forceinline__ void fma2(unsigned long long& d, unsigned long long a,
                                     unsigned long long b) {
    asm("fma.rn.f32x2 %0, %1, %2, %0;" : "+l"(d) : "l"(a), "l"(b));
}
__device__ __forceinline__ void mul2(unsigned long long& a, unsigned long long b) {
    asm("mul.rn.f32x2 %0, %0, %1;" : "+l"(a) : "l"(b));
}
__device__ __forceinline__ unsigned long long dup2(float x) {
    unsigned long long r;
    asm("mov.b64 %0, {%1, %1};" : "=l"(r) : "f"(x));
    return r;
}
__device__ __forceinline__ float2 unpack2(unsigned long long p) {
    float2 r;
    asm("mov.b64 {%0, %1}, %2;" : "=f"(r.x), "=f"(r.y) : "l"(p));
    return r;
}

// ---------------- im2col: x[64,1,256,256] -> patches[16384, 256] -----------
__global__ void im2col_kernel(const float* __restrict__ x, float* __restrict__ P) {
    int idx = blockIdx.x * 256 + threadIdx.x;   // 4,194,304 total
    int p = idx & 255, r = idx >> 8;
    int px = p & 15, py = p >> 4;
    int t = r & 255, b = r >> 8;
    int tx = t & 15, ty = t >> 4;
    P[idx] = x[(size_t)b * 65536 + (size_t)(ty * 16 + py) * 256 + tx * 16 + px];
}

// ---------------- conv_w [1024,256] -> Wt [256,1024] -----------------------
__global__ void wtrans_kernel(const float* __restrict__ W, float* __restrict__ Wt) {
    int idx = blockIdx.x * 256 + threadIdx.x;   // 262,144 total
    int c = idx & 1023, p = idx >> 10;
    Wt[idx] = W[c * 256 + p];
}

// ---------------- sgemm: C = A[M,K] @ B[K,N] + bias ------------------------
// 128x128 tile, BK=16, 256 threads, 8x8 micro-tile (split 4+4), f32x2 FMAs.
// mode 0: C row-major [M,N].  mode 1: head layout C[((b*8+h)*256+t)*128+d].
__global__ void __launch_bounds__(256) sgemm_kernel(
    const float* __restrict__ A, const float* __restrict__ B,
    const float* __restrict__ bias, float* __restrict__ C,
    int M, int N, int K, int mode)
{
    __shared__ float As[16][128];
    __shared__ float Bs[16][128];

    const int tid = threadIdx.x;
    const int m0 = blockIdx.y * 128, n0 = blockIdx.x * 128;
    const int ty = tid >> 4, tx = tid & 15;

    const int arow = tid >> 2;            // 0..63
    const int acol = (tid & 3) << 2;      // 0,4,8,12
    const int brow = tid >> 5;            // 0..7
    const int bcol = (tid & 31) << 2;     // 0..124

    const float* Ag = A + (size_t)(m0 + arow) * K + acol;
    const float* Bg = B + (size_t)brow * N + n0 + bcol;

    unsigned long long accp[2][4][2][2];
    #pragma unroll
    for (int ia = 0; ia < 2; ia++)
        #pragma unroll
        for (int i = 0; i < 4; i++)
            #pragma unroll
            for (int ib = 0; ib < 2; ib++) {
                accp[ia][i][ib][0] = 0ull;
                accp[ia][i][ib][1] = 0ull;
            }

    // prologue loads (tile 0)
    float4 a0 = *(const float4*)(Ag);
    float4 a1 = *(const float4*)(Ag + (size_t)64 * K);
    float4 b0 = *(const float4*)(Bg);
    float4 b1 = *(const float4*)(Bg + (size_t)8 * N);
    Ag += 16;
    Bg += (size_t)16 * N;

    for (int kt = 0; kt < K; kt += 16) {
        __syncthreads();   // previous compute done
        As[acol + 0][arow] = a0.x;  As[acol + 1][arow] = a0.y;
        As[acol + 2][arow] = a0.z;  As[acol + 3][arow] = a0.w;
        As[acol + 0][64 + arow] = a1.x;  As[acol + 1][64 + arow] = a1.y;
        As[acol + 2][64 + arow] = a1.z;  As[acol + 3][64 + arow] = a1.w;
        *(float4*)&Bs[brow][bcol] = b0;
        *(float4*)&Bs[brow + 8][bcol] = b1;
        __syncthreads();

        if (kt + 16 < K) {   // pipeline next tile's loads over compute
            a0 = *(const float4*)(Ag);
            a1 = *(const float4*)(Ag + (size_t)64 * K);
            b0 = *(const float4*)(Bg);
            b1 = *(const float4*)(Bg + (size_t)8 * N);
            Ag += 16;
            Bg += (size_t)16 * N;
        }

        #pragma unroll
        for (int kk = 0; kk < 16; kk++) {
            float4 af0 = *(const float4*)&As[kk][ty * 4];
            float4 af1 = *(const float4*)&As[kk][64 + ty * 4];
            ulonglong2 bp0 = *(const ulonglong2*)&Bs[kk][tx * 4];
            ulonglong2 bp1 = *(const ulonglong2*)&Bs[kk][64 + tx * 4];
            float a_[2][4] = {{af0.x, af0.y, af0.z, af0.w},
                              {af1.x, af1.y, af1.z, af1.w}};
            #pragma unroll
            for (int ia = 0; ia < 2; ia++)
                #pragma unroll
                for (int i = 0; i < 4; i++) {
                    unsigned long long ad = dup2(a_[ia][i]);
                    fma2(accp[ia][i][0][0], ad, bp0.x);
                    fma2(accp[ia][i][0][1], ad, bp0.y);
                    fma2(accp[ia][i][1][0], ad, bp1.x);
                    fma2(accp[ia][i][1][1], ad, bp1.y);
                }
        }
    }

    // epilogue
    #pragma unroll
    for (int ia = 0; ia < 2; ia++)
        #pragma unroll
        for (int i = 0; i < 4; i++) {
            int row = m0 + ia * 64 + ty * 4 + i;
            #pragma unroll
            for (int ib = 0; ib < 2; ib++) {
                int col = n0 + ib * 64 + tx * 4;
                float2 p0 = unpack2(accp[ia][i][ib][0]);
                float2 p1 = unpack2(accp[ia][i][ib][1]);
                float4 bb = *(const float4*)&bias[col];
                float4 r;
                r.x = p0.x + bb.x; r.y = p0.y + bb.y;
                r.z = p1.x + bb.z; r.w = p1.y + bb.w;
                size_t off;
                if (mode == 0) {
                    off = (size_t)row * N + col;
                } else {
                    int b = row >> 8, t = row & 255;
                    int h = col >> 7, d = col & 127;
                    off = ((size_t)(b * 8 + h) * 256 + (size_t)t) * 128 + d;
                }
                *(float4*)&C[off] = r;
            }
        }
}

// ---------------- fused causal attention (flash-style) ---------------------
// grid (512 bh, 4 qtiles), 256 threads. q/k/v: [BH, 256, 128]. out: [B,T,C].
__global__ void __launch_bounds__(256) attn_kernel(
    const float* __restrict__ Q, const float* __restrict__ Kp,
    const float* __restrict__ Vp, float* __restrict__ Y)
{
    extern __shared__ float sm[];
    float* Qs = sm;                 // 64 x 132 (padded)
    float* Kt = sm + 64 * 132;      // 128 x 68 (transposed, padded)
    float* Vs = Kt + 128 * 68;      // 64 x 128
    float* Ss = Vs + 64 * 128;      // 64 x 65 (padded)

    const int bh = blockIdx.x, qt = blockIdx.y;
    const int tid = threadIdx.x;
    const int ty = tid >> 4, tx = tid & 15;
    const float scale = 0.08838834764831845f;   // 1/sqrt(128)

    const float* qg = Q + ((size_t)bh * 256 + qt * 64) * 128;
    #pragma unroll
    for (int i = 0; i < 8; i++) {
        int e = tid + i * 256;
        int row = e >> 5, c = (e & 31) << 2;
        float4 qv = *(const float4*)&qg[row * 128 + c];
        float* d = &Qs[row * 132 + c];
        d[0] = qv.x * scale; d[1] = qv.y * scale;
        d[2] = qv.z * scale; d[3] = qv.w * scale;
    }

    unsigned long long accp[4][4];
    #pragma unroll
    for (int i = 0; i < 4; i++)
        #pragma unroll
        for (int j = 0; j < 4; j++) accp[i][j] = 0ull;
    float mrow[4] = {-1e30f, -1e30f, -1e30f, -1e30f};
    float lrow[4] = {0.f, 0.f, 0.f, 0.f};

    for (int jt = 0; jt <= qt; jt++) {
        __syncthreads();   // prev PV reads done (and Qs visible on iter 0)
        const float* kg = Kp + ((size_t)bh * 256 + jt * 64) * 128;
        const float* vg = Vp + ((size_t)bh * 256 + jt * 64) * 128;
        #pragma unroll
        for (int i = 0; i < 8; i++) {
            int e = tid + i * 256;
            int row = e >> 5, c = (e & 31) << 2;
            float4 kv = *(const float4*)&kg[row * 128 + c];
            Kt[(c + 0) * 68 + row] = kv.x;
            Kt[(c + 1) * 68 + row] = kv.y;
            Kt[(c + 2) * 68 + row] = kv.z;
            Kt[(c + 3) * 68 + row] = kv.w;
            *(float4*)&Vs[row * 128 + c] = *(const float4*)&vg[row * 128 + c];
        }
        __syncthreads();

        // S = Q * K^T (per-thread 4x4 tile)
        unsigned long long sp[4][2];
        #pragma unroll
        for (int i = 0; i < 4; i++) { sp[i][0] = 0ull; sp[i][1] = 0ull; }
        #pragma unroll 8
        for (int d = 0; d < 128; d++) {
            ulonglong2 kp2 = *(const ulonglong2*)&Kt[d * 68 + tx * 4];
            #pragma unroll
            for (int i = 0; i < 4; i++) {
                unsigned long long qd = dup2(Qs[(ty * 4 + i) * 132 + d]);
                fma2(sp[i][0], qd, kp2.x);
                fma2(sp[i][1], qd, kp2.y);
            }
        }
        float s[4][4];
        #pragma unroll
        for (int i = 0; i < 4; i++) {
            float2 u0 = unpack2(sp[i][0]), u1 = unpack2(sp[i][1]);
            s[i][0] = u0.x; s[i][1] = u0.y; s[i][2] = u1.x; s[i][3] = u1.y;
        }
        if (jt == qt) {
            #pragma unroll
            for (int i = 0; i < 4; i++)
                #pragma unroll
                for (int j = 0; j < 4; j++)
                    if (tx * 4 + j > ty * 4 + i) s[i][j] = -1e30f;
        }
        #pragma unroll
        for (int i = 0; i < 4; i++) {
            float mx = fmaxf(fmaxf(s[i][0], s[i][1]), fmaxf(s[i][2], s[i][3]));
            mx = fmaxf(mx, __shfl_xor_sync(0xffffffffu, mx, 1, 16));
            mx = fmaxf(mx, __shfl_xor_sync(0xffffffffu, mx, 2, 16));
            mx = fmaxf(mx, __shfl_xor_sync(0xffffffffu, mx, 4, 16));
            mx = fmaxf(mx, __shfl_xor_sync(0xffffffffu, mx, 8, 16));
            float mnew = fmaxf(mrow[i], mx);
            float alpha = __expf(mrow[i] - mnew);
            float rs = 0.f;
            #pragma unroll
            for (int j = 0; j < 4; j++) {
                float p = __expf(s[i][j] - mnew);
                s[i][j] = p;
                rs += p;
            }
            rs += __shfl_xor_sync(0xffffffffu, rs, 1, 16);
            rs += __shfl_xor_sync(0xffffffffu, rs, 2, 16);
            rs += __shfl_xor_sync(0xffffffffu, rs, 4, 16);
            rs += __shfl_xor_sync(0xffffffffu, rs, 8, 16);
            lrow[i] = lrow[i] * alpha + rs;
            mrow[i] = mnew;
            unsigned long long av = dup2(alpha);
            mul2(accp[i][0], av); mul2(accp[i][1], av);
            mul2(accp[i][2], av); mul2(accp[i][3], av);
            float* sr = &Ss[(ty * 4 + i) * 65 + tx * 4];
            sr[0] = s[i][0]; sr[1] = s[i][1]; sr[2] = s[i][2]; sr[3] = s[i][3];
        }
        __syncthreads();

        // O += P * V
        #pragma unroll 4
        for (int jj = 0; jj < 64; jj++) {
            ulonglong2 v0 = *(const ulonglong2*)&Vs[jj * 128 + tx * 4];
            ulonglong2 v1 = *(const ulonglong2*)&Vs[jj * 128 + 64 + tx * 4];
            #pragma unroll
            for (int i = 0; i < 4; i++) {
                unsigned long long pd = dup2(Ss[(ty * 4 + i) * 65 + jj]);
                fma2(accp[i][0], pd, v0.x);
                fma2(accp[i][1], pd, v0.y);
                fma2(accp[i][2], pd, v1.x);
                fma2(accp[i][3], pd, v1.y);
            }
        }
    }

    // write y in [B, T, C] layout
    const int b = bh >> 3, h = bh & 7;
    #pragma unroll
    for (int i = 0; i < 4; i++) {
        float inv = 1.0f / lrow[i];
        int t = qt * 64 + ty * 4 + i;
        float* yb = Y + ((size_t)(b * 256 + t)) * 1024 + h * 128;
        float2 p0 = unpack2(accp[i][0]), p1 = unpack2(accp[i][1]);
        float2 p2 = unpack2(accp[i][2]), p3 = unpack2(accp[i][3]);
        float4 r0 = {p0.x * inv, p0.y * inv, p1.x * inv, p1.y * inv};
        float4 r1 = {p2.x * inv, p2.y * inv, p3.x * inv, p3.y * inv};
        *(float4*)&yb[tx * 4] = r0;
        *(float4*)&yb[64 + tx * 4] = r1;
    }
}

// ---------------- launcher --------------------------------------------------
extern "C" void kernel_launch(void* const* d_in, const int* in_sizes, int n_in,
                              void* d_out, int out_size) {
    const float* x      = (const float*)d_in[0];
    const float* conv_w = (const float*)d_in[1];
    const float* conv_b = (const float*)d_in[2];
    const float* Wq     = (const float*)d_in[3];
    const float* bq     = (const float*)d_in[4];
    const float* Wk     = (const float*)d_in[5];
    const float* bk     = (const float*)d_in[6];
    const float* Wv     = (const float*)d_in[7];
    const float* bv     = (const float*)d_in[8];
    const float* Wp     = (const float*)d_in[9];
    const float* bp     = (const float*)d_in[10];
    float* out = (float*)d_out;

    const size_t YN = (size_t)64 * 256 * 1024;   // 16,777,216
    float* kout = out + YN;            // present[0] = k, [B,H,T,D]
    float* vout = out + 2 * YN;        // present[1] = v

    float *patches, *wt, *tok, *q, *yh;
    cudaGetSymbolAddress((void**)&patches, g_patches);
    cudaGetSymbolAddress((void**)&wt, g_wt);
    cudaGetSymbolAddress((void**)&tok, g_tok);
    cudaGetSymbolAddress((void**)&q, g_q);
    cudaGetSymbolAddress((void**)&yh, g_y);

    const int ATTN_SMEM = (64 * 132 + 128 * 68 + 64 * 128 + 64 * 65) * 4;  // 118016
    cudaFuncSetAttribute(attn_kernel, cudaFuncAttributeMaxDynamicSharedMemorySize,
                         ATTN_SMEM);

    im2col_kernel<<<16384, 256>>>(x, patches);
    wtrans_kernel<<<1024, 256>>>(conv_w, wt);

    dim3 g(1024 / 128, 16384 / 128);   // (8, 128)
    // tok = patches @ Wt + conv_b
    sgemm_kernel<<<g, 256>>>(patches, wt, conv_b, tok, 16384, 1024, 256, 0);
    // q/k/v (head layout); k, v written directly into d_out (present)
    sgemm_kernel<<<g, 256>>>(tok, Wq, bq, q,    16384, 1024, 1024, 1);
    sgemm_kernel<<<g, 256>>>(tok, Wk, bk, kout, 16384, 1024, 1024, 1);
    sgemm_kernel<<<g, 256>>>(tok, Wv, bv, vout, 16384, 1024, 1024, 1);
    // attention
    attn_kernel<<<dim3(512, 4), 256, ATTN_SMEM>>>(q, kout, vout, yh);
    // y = yh @ Wp + bp
    sgemm_kernel<<<g, 256>>>(yh, Wp, bp, out, 16384, 1024, 1024, 0);
}

// round 3
// speedup vs baseline: 2.2318x; 2.2318x over previous
#include <cuda_runtime.h>
#include <cuda_bf16.h>
#include <cstdint>

// ======================= scratch (device globals) ==========================
__device__ __nv_bfloat16 g_phi[16384 * 256];      // im2col patches hi
__device__ __nv_bfloat16 g_plo[16384 * 256];      // im2col patches lo
__device__ __nv_bfloat16 g_wchi[1024 * 256];      // conv_w split hi [N,K]
__device__ __nv_bfloat16 g_wclo[1024 * 256];
__device__ __nv_bfloat16 g_wthi[4 * 1024 * 1024]; // Wq,Wk,Wv,Wp transposed [N,K]
__device__ __nv_bfloat16 g_wtlo[4 * 1024 * 1024];
__device__ __nv_bfloat16 g_tokhi[16384 * 1024];
__device__ __nv_bfloat16 g_toklo[16384 * 1024];
__device__ float         g_q[16384 * 1024];       // q fp32 [B,H,T,D]
__device__ __nv_bfloat16 g_yhi[16384 * 1024];     // attn out hi [B,T,C]
__device__ __nv_bfloat16 g_ylo[16384 * 1024];

// ======================= small helpers ======================================
__device__ __forceinline__ uint32_t smem_u32(const void* p) {
    uint32_t a;
    asm("{ .reg .u64 t; cvta.to.shared.u64 t, %1; cvt.u32.u64 %0, t; }"
        : "=r"(a) : "l"(p));
    return a;
}
__device__ __forceinline__ void cp_async16(uint32_t saddr, const void* gaddr) {
    asm volatile("cp.async.cg.shared.global [%0], [%1], 16;"
                 :: "r"(saddr), "l"(gaddr));
}
__device__ __forceinline__ void cp_commit() {
    asm volatile("cp.async.commit_group;");
}
__device__ __forceinline__ void cp_wait1() {
    asm volatile("cp.async.wait_group 1;");
}
__device__ __forceinline__ void ldsm_x4(uint32_t* r, uint32_t addr) {
    asm volatile("ldmatrix.sync.aligned.m8n8.x4.shared.b16 {%0,%1,%2,%3}, [%4];"
                 : "=r"(r[0]), "=r"(r[1]), "=r"(r[2]), "=r"(r[3]) : "r"(addr));
}
__device__ __forceinline__ void mma_bf16(float4& d, const uint32_t a[4],
                                         uint32_t b0, uint32_t b1) {
    asm volatile(
        "mma.sync.aligned.m16n8k16.row.col.f32.bf16.bf16.f32 "
        "{%0,%1,%2,%3}, {%4,%5,%6,%7}, {%8,%9}, {%0,%1,%2,%3};"
        : "+f"(d.x), "+f"(d.y), "+f"(d.z), "+f"(d.w)
        : "r"(a[0]), "r"(a[1]), "r"(a[2]), "r"(a[3]), "r"(b0), "r"(b1));
}
__device__ __forceinline__ uint32_t swz64(uint32_t x) {
    return x ^ ((x >> 3) & 0x30);
}
__device__ __forceinline__ void split_bf16(float v, __nv_bfloat16& hi, __nv_bfloat16& lo) {
    hi = __float2bfloat16(v);
    lo = __float2bfloat16(v - __bfloat162float(hi));
}
__device__ __forceinline__ uint32_t pack_bf16(float a, float b) {
    __nv_bfloat162 p = __floats2bfloat162_rn(a, b);
    return *reinterpret_cast<uint32_t*>(&p);
}

// ---------------- packed f32x2 helpers (attention) --------------------------
__device__ __forceinline__ void fma2(unsigned long long& d, unsigned long long a,
                                     unsigned long long b) {
    asm("fma.rn.f32x2 %0, %1, %2, %0;" : "+l"(d) : "l"(a), "l"(b));
}
__device__ __forceinline__ void mul2(unsigned long long& a, unsigned long long b) {
    asm("mul.rn.f32x2 %0, %0, %1;" : "+l"(a) : "l"(b));
}
__device__ __forceinline__ unsigned long long dup2(float x) {
    unsigned long long r;
    asm("mov.b64 %0, {%1, %1};" : "=l"(r) : "f"(x));
    return r;
}
__device__ __forceinline__ float2 unpack2(unsigned long long p) {
    float2 r;
    asm("mov.b64 {%0, %1}, %2;" : "=f"(r.x), "=f"(r.y) : "l"(p));
    return r;
}

// ======================= prep kernels =======================================
__global__ void im2col_split(const float* __restrict__ x,
                             __nv_bfloat16* __restrict__ Phi,
                             __nv_bfloat16* __restrict__ Plo) {
    int idx = blockIdx.x * 256 + threadIdx.x;
    int p = idx & 255, r = idx >> 8;
    int px = p & 15, py = p >> 4;
    int t = r & 255, b = r >> 8;
    int tx = t & 15, ty = t >> 4;
    float v = x[(size_t)b * 65536 + (size_t)(ty * 16 + py) * 256 + tx * 16 + px];
    __nv_bfloat16 h, l; split_bf16(v, h, l);
    Phi[idx] = h; Plo[idx] = l;
}

__global__ void split_elem(const float* __restrict__ W,
                           __nv_bfloat16* __restrict__ H,
                           __nv_bfloat16* __restrict__ L) {
    int idx = blockIdx.x * 256 + threadIdx.x;
    __nv_bfloat16 h, l; split_bf16(W[idx], h, l);
    H[idx] = h; L[idx] = l;
}

__global__ void wtrans_split(const float* __restrict__ W,
                             __nv_bfloat16* __restrict__ Thi,
                             __nv_bfloat16* __restrict__ Tlo) {
    __shared__ float t[32][33];
    int kb = blockIdx.x * 32, nb = blockIdx.y * 32;
    int x = threadIdx.x, y = threadIdx.y;  // 32 x 8
    #pragma unroll
    for (int i = 0; i < 32; i += 8)
        t[y + i][x] = W[(size_t)(kb + y + i) * 1024 + nb + x];
    __syncthreads();
    #pragma unroll
    for (int i = 0; i < 32; i += 8) {
        float v = t[x][y + i];
        int n = nb + y + i, k = kb + x;
        __nv_bfloat16 h, l; split_bf16(v, h, l);
        Thi[(size_t)n * 1024 + k] = h;
        Tlo[(size_t)n * 1024 + k] = l;
    }
}

// ======================= mma.sync split-bf16 GEMM ===========================
// C[M,N] = A[M,K] @ B^T (B stored [N,K], K contiguous), fp32 accum via
// Ah*Bh + Ah*Bl + Al*Bh. CTA tile 128x128, BK=32, 3-stage cp.async pipeline.
// 8 warps: warp_m = wid&3 (32 rows), warp_n = wid>>2 (64 cols).
// mode 0: fp32 row-major + bias. mode 1: fp32 head layout + bias.
// mode 2: bf16 hi/lo row-major + bias.
__global__ void __launch_bounds__(256, 2) tc_gemm(
    const __nv_bfloat16* __restrict__ Ahi, const __nv_bfloat16* __restrict__ Alo,
    const __nv_bfloat16* __restrict__ Bhi, const __nv_bfloat16* __restrict__ Blo,
    const float* __restrict__ bias, float* __restrict__ C,
    __nv_bfloat16* __restrict__ Chi, __nv_bfloat16* __restrict__ Clo,
    int M, int N, int K, int mode)
{
    extern __shared__ char smem[];
    const uint32_t sb = smem_u32(smem);
    const int tid = threadIdx.x, wid = tid >> 5, lane = tid & 31;
    const int m0 = blockIdx.y * 128, n0 = blockIdx.x * 128;

    // stage layout: Ah[8K] Al[8K] Bh[8K] Bl[8K] = 32KB per stage, 3 stages
    const uint32_t STG = 32768;

    // global-load mapping: 2 chunks of 16B per array per thread
    const int row0 = tid >> 2;          // 0..63
    const int row1 = row0 + 64;         // 64..127
    const int seg = tid & 3;            // 16B segment within 64B row
    const uint32_t soff0 = swz64(row0 * 64 + seg * 16);
    const uint32_t soff1 = swz64(row1 * 64 + seg * 16);

    const __nv_bfloat16* Ah_g = Ahi + (size_t)(m0 + row0) * K + seg * 8;
    const __nv_bfloat16* Al_g = Alo + (size_t)(m0 + row0) * K + seg * 8;
    const __nv_bfloat16* Bh_g = Bhi + (size_t)(n0 + row0) * K + seg * 8;
    const __nv_bfloat16* Bl_g = Blo + (size_t)(n0 + row0) * K + seg * 8;
    const size_t rstep = (size_t)64 * K;

    const int NK = K >> 5;   // k32 chunks

    auto issue_stage = [&](int kt) {
        const uint32_t s = sb + (kt % 3) * STG;
        const size_t ko = (size_t)kt * 32;
        cp_async16(s + soff0,         Ah_g + ko);
        cp_async16(s + soff1,         Ah_g + ko + rstep);
        cp_async16(s + 8192  + soff0, Al_g + ko);
        cp_async16(s + 8192  + soff1, Al_g + ko + rstep);
        cp_async16(s + 16384 + soff0, Bh_g + ko);
        cp_async16(s + 16384 + soff1, Bh_g + ko + rstep);
        cp_async16(s + 24576 + soff0, Bl_g + ko);
        cp_async16(s + 24576 + soff1, Bl_g + ko + rstep);
    };

    issue_stage(0); cp_commit();
    issue_stage(1); cp_commit();

    // ldmatrix per-lane address offsets (within a stage)
    const int wm = (wid & 3) * 32;      // warp m-origin (local)
    const int wn = (wid >> 2) * 64;     // warp n-origin (local)
    // A x4: lanes 0-15 rows, lanes 16-31 rows at +16B
    const int a_row = wm + (lane & 15);
    const int a_kb = (lane >> 4) * 16;
    // B x4: lanes 0-7 n0-7@k0, 8-15 n0-7@+16B, 16-23 n8-15@k0, 24-31 n8-15@+16B
    const int b_row = wn + (lane & 7) + ((lane >> 4) & 1) * 8;
    const int b_kb = ((lane >> 3) & 1) * 16;

    float4 acc[2][8];
    #pragma unroll
    for (int i = 0; i < 2; i++)
        #pragma unroll
        for (int j = 0; j < 8; j++) acc[i][j] = make_float4(0.f, 0.f, 0.f, 0.f);

    for (int kt = 0; kt < NK; kt++) {
        cp_wait1();
        __syncthreads();
        if (kt + 2 < NK) issue_stage(kt + 2);
        cp_commit();

        const uint32_t s = sb + (kt % 3) * STG;
        #pragma unroll
        for (int kb = 0; kb < 2; kb++) {
            uint32_t ah[2][4], al[2][4];
            #pragma unroll
            for (int mi = 0; mi < 2; mi++) {
                uint32_t off = swz64((a_row + mi * 16) * 64 + kb * 32 + a_kb);
                ldsm_x4(ah[mi], s + off);
                ldsm_x4(al[mi], s + 8192 + off);
            }
            #pragma unroll
            for (int g = 0; g < 4; g++) {
                uint32_t bh[4], bl[4];
                uint32_t off = swz64((b_row + g * 16) * 64 + kb * 32 + b_kb);
                ldsm_x4(bh, s + 16384 + off);
                ldsm_x4(bl, s + 24576 + off);
                #pragma unroll
                for (int mi = 0; mi < 2; mi++) {
                    mma_bf16(acc[mi][2 * g],     ah[mi], bh[0], bh[1]);
                    mma_bf16(acc[mi][2 * g],     ah[mi], bl[0], bl[1]);
                    mma_bf16(acc[mi][2 * g],     al[mi], bh[0], bh[1]);
                    mma_bf16(acc[mi][2 * g + 1], ah[mi], bh[2], bh[3]);
                    mma_bf16(acc[mi][2 * g + 1], ah[mi], bl[2], bl[3]);
                    mma_bf16(acc[mi][2 * g + 1], al[mi], bh[2], bh[3]);
                }
            }
        }
        __syncthreads();
    }

    // ---- epilogue ----
    // frag (mi, ni): rows r = m0+wm+mi*16+(lane>>2) (+8), cols c = n0+wn+ni*8+(lane&3)*2
    #pragma unroll
    for (int mi = 0; mi < 2; mi++) {
        const int ra = m0 + wm + mi * 16 + (lane >> 2);
        const int rb = ra + 8;
        #pragma unroll
        for (int ni = 0; ni < 8; ni++) {
            const int c = n0 + wn + ni * 8 + (lane & 3) * 2;
            const float bx = bias[c], by = bias[c + 1];
            float4 v = acc[mi][ni];
            v.x += bx; v.y += by; v.z += bx; v.w += by;
            if (mode == 0) {
                *(float2*)&C[(size_t)ra * N + c] = make_float2(v.x, v.y);
                *(float2*)&C[(size_t)rb * N + c] = make_float2(v.z, v.w);
            } else if (mode == 1) {
                const int h = c >> 7, d = c & 127;
                const int ba_ = ra >> 8, ta = ra & 255;
                const int bb_ = rb >> 8, tb = rb & 255;
                float* pa = C + (((size_t)(ba_ * 8 + h) * 256 + ta) * 128 + d);
                float* pb = C + (((size_t)(bb_ * 8 + h) * 256 + tb) * 128 + d);
                *(float2*)pa = make_float2(v.x, v.y);
                *(float2*)pb = make_float2(v.z, v.w);
            } else {
                float hx, hy, hz, hw, lx, ly, lz, lw;
                {
                    __nv_bfloat16 h_, l_;
                    split_bf16(v.x, h_, l_); hx = __bfloat162float(h_); lx = __bfloat162float(l_);
                    split_bf16(v.y, h_, l_); hy = __bfloat162float(h_); ly = __bfloat162float(l_);
                    split_bf16(v.z, h_, l_); hz = __bfloat162float(h_); lz = __bfloat162float(l_);
                    split_bf16(v.w, h_, l_); hw = __bfloat162float(h_); lw = __bfloat162float(l_);
                }
                *(uint32_t*)&Chi[(size_t)ra * N + c] = pack_bf16(hx, hy);
                *(uint32_t*)&Clo[(size_t)ra * N + c] = pack_bf16(lx, ly);
                *(uint32_t*)&Chi[(size_t)rb * N + c] = pack_bf16(hz, hw);
                *(uint32_t*)&Clo[(size_t)rb * N + c] = pack_bf16(lz, lw);
            }
        }
    }
}

// ======================= fused causal attention (fp32) ======================
__global__ void __launch_bounds__(256) attn_kernel(
    const float* __restrict__ Q, const float* __restrict__ Kp,
    const float* __restrict__ Vp,
    __nv_bfloat16* __restrict__ Yhi, __nv_bfloat16* __restrict__ Ylo)
{
    extern __shared__ float sm[];
    float* Qs = sm;                 // 64 x 132
    float* Kt = sm + 64 * 132;      // 128 x 68
    float* Vs = Kt + 128 * 68;      // 64 x 128
    float* Ss = Vs + 64 * 128;      // 64 x 65

    const int bh = blockIdx.x, qt = blockIdx.y;
    const int tid = threadIdx.x;
    const int ty = tid >> 4, tx = tid & 15;
    const float scale = 0.08838834764831845f;

    const float* qg = Q + ((size_t)bh * 256 + qt * 64) * 128;
    #pragma unroll
    for (int i = 0; i < 8; i++) {
        int e = tid + i * 256;
        int row = e >> 5, c = (e & 31) << 2;
        float4 qv = *(const float4*)&qg[row * 128 + c];
        float* d = &Qs[row * 132 + c];
        d[0] = qv.x * scale; d[1] = qv.y * scale;
        d[2] = qv.z * scale; d[3] = qv.w * scale;
    }

    unsigned long long accp[4][4];
    #pragma unroll
    for (int i = 0; i < 4; i++)
        #pragma unroll
        for (int j = 0; j < 4; j++) accp[i][j] = 0ull;
    float mrow[4] = {-1e30f, -1e30f, -1e30f, -1e30f};
    float lrow[4] = {0.f, 0.f, 0.f, 0.f};

    for (int jt = 0; jt <= qt; jt++) {
        __syncthreads();
        const float* kg = Kp + ((size_t)bh * 256 + jt * 64) * 128;
        const float* vg = Vp + ((size_t)bh * 256 + jt * 64) * 128;
        #pragma unroll
        for (int i = 0; i < 8; i++) {
            int e = tid + i * 256;
            int row = e >> 5, c = (e & 31) << 2;
            float4 kv = *(const float4*)&kg[row * 128 + c];
            Kt[(c + 0) * 68 + row] = kv.x;
            Kt[(c + 1) * 68 + row] = kv.y;
            Kt[(c + 2) * 68 + row] = kv.z;
            Kt[(c + 3) * 68 + row] = kv.w;
            *(float4*)&Vs[row * 128 + c] = *(const float4*)&vg[row * 128 + c];
        }
        __syncthreads();

        unsigned long long spv[4][2];
        #pragma unroll
        for (int i = 0; i < 4; i++) { spv[i][0] = 0ull; spv[i][1] = 0ull; }
        #pragma unroll 8
        for (int d = 0; d < 128; d++) {
            ulonglong2 kp2 = *(const ulonglong2*)&Kt[d * 68 + tx * 4];
            #pragma unroll
            for (int i = 0; i < 4; i++) {
                unsigned long long qd = dup2(Qs[(ty * 4 + i) * 132 + d]);
                fma2(spv[i][0], qd, kp2.x);
                fma2(spv[i][1], qd, kp2.y);
            }
        }
        float s[4][4];
        #pragma unroll
        for (int i = 0; i < 4; i++) {
            float2 u0 = unpack2(spv[i][0]), u1 = unpack2(spv[i][1]);
            s[i][0] = u0.x; s[i][1] = u0.y; s[i][2] = u1.x; s[i][3] = u1.y;
        }
        if (jt == qt) {
            #pragma unroll
            for (int i = 0; i < 4; i++)
                #pragma unroll
                for (int j = 0; j < 4; j++)
                    if (tx * 4 + j > ty * 4 + i) s[i][j] = -1e30f;
        }
        #pragma unroll
        for (int i = 0; i < 4; i++) {
            float mx = fmaxf(fmaxf(s[i][0], s[i][1]), fmaxf(s[i][2], s[i][3]));
            mx = fmaxf(mx, __shfl_xor_sync(0xffffffffu, mx, 1, 16));
            mx = fmaxf(mx, __shfl_xor_sync(0xffffffffu, mx, 2, 16));
            mx = fmaxf(mx, __shfl_xor_sync(0xffffffffu, mx, 4, 16));
            mx = fmaxf(mx, __shfl_xor_sync(0xffffffffu, mx, 8, 16));
            float mnew = fmaxf(mrow[i], mx);
            float alpha = __expf(mrow[i] - mnew);
            float rs = 0.f;
            #pragma unroll
            for (int j = 0; j < 4; j++) {
                float p = __expf(s[i][j] - mnew);
                s[i][j] = p;
                rs += p;
            }
            rs += __shfl_xor_sync(0xffffffffu, rs, 1, 16);
            rs += __shfl_xor_sync(0xffffffffu, rs, 2, 16);
            rs += __shfl_xor_sync(0xffffffffu, rs, 4, 16);
            rs += __shfl_xor_sync(0xffffffffu, rs, 8, 16);
            lrow[i] = lrow[i] * alpha + rs;
            mrow[i] = mnew;
            unsigned long long av = dup2(alpha);
            mul2(accp[i][0], av); mul2(accp[i][1], av);
            mul2(accp[i][2], av); mul2(accp[i][3], av);
            float* sr = &Ss[(ty * 4 + i) * 65 + tx * 4];
            sr[0] = s[i][0]; sr[1] = s[i][1]; sr[2] = s[i][2]; sr[3] = s[i][3];
        }
        __syncthreads();

        #pragma unroll 4
        for (int jj = 0; jj < 64; jj++) {
            ulonglong2 v0 = *(const ulonglong2*)&Vs[jj * 128 + tx * 4];
            ulonglong2 v1 = *(const ulonglong2*)&Vs[jj * 128 + 64 + tx * 4];
            #pragma unroll
            for (int i = 0; i < 4; i++) {
                unsigned long long pd = dup2(Ss[(ty * 4 + i) * 65 + jj]);
                fma2(accp[i][0], pd, v0.x);
                fma2(accp[i][1], pd, v0.y);
                fma2(accp[i][2], pd, v1.x);
                fma2(accp[i][3], pd, v1.y);
            }
        }
    }

    const int b = bh >> 3, h = bh & 7;
    #pragma unroll
    for (int i = 0; i < 4; i++) {
        float inv = 1.0f / lrow[i];
        int t = qt * 64 + ty * 4 + i;
        size_t base = ((size_t)(b * 256 + t)) * 1024 + h * 128;
        float2 p0 = unpack2(accp[i][0]), p1 = unpack2(accp[i][1]);
        float2 p2 = unpack2(accp[i][2]), p3 = unpack2(accp[i][3]);
        float vals[8] = {p0.x * inv, p0.y * inv, p1.x * inv, p1.y * inv,
                         p2.x * inv, p2.y * inv, p3.x * inv, p3.y * inv};
        #pragma unroll
        for (int seg = 0; seg < 2; seg++) {
            size_t o = base + seg * 64 + tx * 4;
            #pragma unroll
            for (int j = 0; j < 4; j++) {
                __nv_bfloat16 hh, ll;
                split_bf16(vals[seg * 4 + j], hh, ll);
                Yhi[o + j] = hh;
                Ylo[o + j] = ll;
            }
        }
    }
}

// ======================= launcher ===========================================
extern "C" void kernel_launch(void* const* d_in, const int* in_sizes, int n_in,
                              void* d_out, int out_size) {
    const float* x      = (const float*)d_in[0];
    const float* conv_w = (const float*)d_in[1];
    const float* conv_b = (const float*)d_in[2];
    const float* Wq     = (const float*)d_in[3];
    const float* bq     = (const float*)d_in[4];
    const float* Wk     = (const float*)d_in[5];
    const float* bk     = (const float*)d_in[6];
    const float* Wv     = (const float*)d_in[7];
    const float* bv     = (const float*)d_in[8];
    const float* Wp     = (const float*)d_in[9];
    const float* bp     = (const float*)d_in[10];
    float* out = (float*)d_out;

    const size_t YN = (size_t)64 * 256 * 1024;
    float* kout = out + YN;
    float* vout = out + 2 * YN;

    __nv_bfloat16 *phi, *plo, *wchi, *wclo, *wthi, *wtlo, *tokhi, *toklo, *yhi, *ylo;
    float* q;
    cudaGetSymbolAddress((void**)&phi, g_phi);
    cudaGetSymbolAddress((void**)&plo, g_plo);
    cudaGetSymbolAddress((void**)&wchi, g_wchi);
    cudaGetSymbolAddress((void**)&wclo, g_wclo);
    cudaGetSymbolAddress((void**)&wthi, g_wthi);
    cudaGetSymbolAddress((void**)&wtlo, g_wtlo);
    cudaGetSymbolAddress((void**)&tokhi, g_tokhi);
    cudaGetSymbolAddress((void**)&toklo, g_toklo);
    cudaGetSymbolAddress((void**)&q, g_q);
    cudaGetSymbolAddress((void**)&yhi, g_yhi);
    cudaGetSymbolAddress((void**)&ylo, g_ylo);

    const int GEMM_SMEM = 3 * 32768;   // 98304
    cudaFuncSetAttribute(tc_gemm, cudaFuncAttributeMaxDynamicSharedMemorySize,
                         GEMM_SMEM);
    const int ATTN_SMEM = (64 * 132 + 128 * 68 + 64 * 128 + 64 * 65) * 4;
    cudaFuncSetAttribute(attn_kernel, cudaFuncAttributeMaxDynamicSharedMemorySize,
                         ATTN_SMEM);

    // prep
    im2col_split<<<16384, 256>>>(x, phi, plo);
    split_elem<<<1024, 256>>>(conv_w, wchi, wclo);
    wtrans_split<<<dim3(32, 32), dim3(32, 8)>>>(Wq, wthi + 0 * 1048576, wtlo + 0 * 1048576);
    wtrans_split<<<dim3(32, 32), dim3(32, 8)>>>(Wk, wthi + 1 * 1048576, wtlo + 1 * 1048576);
    wtrans_split<<<dim3(32, 32), dim3(32, 8)>>>(Wv, wthi + 2 * 1048576, wtlo + 2 * 1048576);
    wtrans_split<<<dim3(32, 32), dim3(32, 8)>>>(Wp, wthi + 3 * 1048576, wtlo + 3 * 1048576);

    dim3 g(8, 128);   // (N/128, M/128)
    // tok = patches @ conv_w^T + conv_b  (bf16 hi/lo out)
    tc_gemm<<<g, 256, GEMM_SMEM>>>(phi, plo, wchi, wclo, conv_b,
                                   nullptr, tokhi, toklo, 16384, 1024, 256, 2);
    // q/k/v in head layout (fp32); k,v straight into d_out (present)
    tc_gemm<<<g, 256, GEMM_SMEM>>>(tokhi, toklo, wthi + 0 * 1048576, wtlo + 0 * 1048576,
                                   bq, q, nullptr, nullptr, 16384, 1024, 1024, 1);
    tc_gemm<<<g, 256, GEMM_SMEM>>>(tokhi, toklo, wthi + 1 * 1048576, wtlo + 1 * 1048576,
                                   bk, kout, nullptr, nullptr, 16384, 1024, 1024, 1);
    tc_gemm<<<g, 256, GEMM_SMEM>>>(tokhi, toklo, wthi + 2 * 1048576, wtlo + 2 * 1048576,
                                   bv, vout, nullptr, nullptr, 16384, 1024, 1024, 1);
    // attention (fp32 in, bf16 hi/lo out)
    attn_kernel<<<dim3(512, 4), 256, ATTN_SMEM>>>(q, kout, vout, yhi, ylo);
    // y = yh @ Wp^T + bp (fp32 out)
    tc_gemm<<<g, 256, GEMM_SMEM>>>(yhi, ylo, wthi + 3 * 1048576, wtlo + 3 * 1048576,
                                   bp, out, nullptr, nullptr, 16384, 1024, 1024, 0);
}

// round 4
// speedup vs baseline: 2.5766x; 1.1545x over previous
#include <cuda_runtime.h>
#include <cuda_bf16.h>
#include <cstdint>

// ======================= scratch (device globals) ==========================
__device__ __nv_bfloat16 g_phi[16384 * 256];
__device__ __nv_bfloat16 g_plo[16384 * 256];
__device__ __nv_bfloat16 g_wchi[1024 * 256];
__device__ __nv_bfloat16 g_wclo[1024 * 256];
__device__ __nv_bfloat16 g_wthi[4 * 1024 * 1024]; // Wq,Wk,Wv,Wp [N,K] K-major
__device__ __nv_bfloat16 g_wtlo[4 * 1024 * 1024];
__device__ __nv_bfloat16 g_tokhi[16384 * 1024];
__device__ __nv_bfloat16 g_toklo[16384 * 1024];
__device__ float         g_q[16384 * 1024];       // q fp32 [B,H,T,D]
__device__ __nv_bfloat16 g_yhi[16384 * 1024];     // attn out hi [B,T,C]
__device__ __nv_bfloat16 g_ylo[16384 * 1024];
__device__ float         g_bqkv[3072];

// ======================= small helpers ======================================
__device__ __forceinline__ uint32_t smem_u32(const void* p) {
    uint32_t a;
    asm("{ .reg .u64 t; cvta.to.shared.u64 t, %1; cvt.u32.u64 %0, t; }"
        : "=r"(a) : "l"(p));
    return a;
}
__device__ __forceinline__ void cp_async16(uint32_t saddr, const void* gaddr) {
    asm volatile("cp.async.cg.shared.global [%0], [%1], 16;"
                 :: "r"(saddr), "l"(gaddr));
}
__device__ __forceinline__ void cp_commit() {
    asm volatile("cp.async.commit_group;");
}
__device__ __forceinline__ void cp_wait1() {
    asm volatile("cp.async.wait_group 1;");
}
__device__ __forceinline__ void ldsm_x4(uint32_t* r, uint32_t addr) {
    asm volatile("ldmatrix.sync.aligned.m8n8.x4.shared.b16 {%0,%1,%2,%3}, [%4];"
                 : "=r"(r[0]), "=r"(r[1]), "=r"(r[2]), "=r"(r[3]) : "r"(addr));
}
__device__ __forceinline__ void ldsm_x4_t(uint32_t* r, uint32_t addr) {
    asm volatile("ldmatrix.sync.aligned.m8n8.x4.trans.shared.b16 {%0,%1,%2,%3}, [%4];"
                 : "=r"(r[0]), "=r"(r[1]), "=r"(r[2]), "=r"(r[3]) : "r"(addr));
}
__device__ __forceinline__ void mma_bf16(float4& d, const uint32_t a[4],
                                         uint32_t b0, uint32_t b1) {
    asm volatile(
        "mma.sync.aligned.m16n8k16.row.col.f32.bf16.bf16.f32 "
        "{%0,%1,%2,%3}, {%4,%5,%6,%7}, {%8,%9}, {%0,%1,%2,%3};"
        : "+f"(d.x), "+f"(d.y), "+f"(d.z), "+f"(d.w)
        : "r"(a[0]), "r"(a[1]), "r"(a[2]), "r"(a[3]), "r"(b0), "r"(b1));
}
__device__ __forceinline__ uint32_t swz64(uint32_t x) {
    return x ^ ((x >> 3) & 0x30);
}
__device__ __forceinline__ void split_bf16(float v, __nv_bfloat16& hi, __nv_bfloat16& lo) {
    hi = __float2bfloat16(v);
    lo = __float2bfloat16(v - __bfloat162float(hi));
}
__device__ __forceinline__ uint32_t pack_bf16(float a, float b) {
    __nv_bfloat162 p = __floats2bfloat162_rn(a, b);
    return *reinterpret_cast<uint32_t*>(&p);
}
// split a float into packed-hi / packed-lo halves (2 floats -> 2 uint32)
__device__ __forceinline__ void split_pack2(float a, float b,
                                            uint32_t& hi, uint32_t& lo) {
    __nv_bfloat16 ha, la, hb, lb;
    split_bf16(a, ha, la);
    split_bf16(b, hb, lb);
    __nv_bfloat162 ph = __nv_bfloat162(ha, hb);
    __nv_bfloat162 pl = __nv_bfloat162(la, lb);
    hi = *reinterpret_cast<uint32_t*>(&ph);
    lo = *reinterpret_cast<uint32_t*>(&pl);
}

// ======================= prep kernels =======================================
__global__ void im2col_split(const float* __restrict__ x,
                             __nv_bfloat16* __restrict__ Phi,
                             __nv_bfloat16* __restrict__ Plo) {
    int idx = blockIdx.x * 256 + threadIdx.x;
    int p = idx & 255, r = idx >> 8;
    int px = p & 15, py = p >> 4;
    int t = r & 255, b = r >> 8;
    int tx = t & 15, ty = t >> 4;
    float v = x[(size_t)b * 65536 + (size_t)(ty * 16 + py) * 256 + tx * 16 + px];
    __nv_bfloat16 h, l; split_bf16(v, h, l);
    Phi[idx] = h; Plo[idx] = l;
}

__global__ void split_elem(const float* __restrict__ W,
                           __nv_bfloat16* __restrict__ H,
                           __nv_bfloat16* __restrict__ L) {
    int idx = blockIdx.x * 256 + threadIdx.x;
    __nv_bfloat16 h, l; split_bf16(W[idx], h, l);
    H[idx] = h; L[idx] = l;
}

// all 4 weights transposed+split in one launch (z selects weight)
__global__ void wtrans_all(const float* __restrict__ W0, const float* __restrict__ W1,
                           const float* __restrict__ W2, const float* __restrict__ W3,
                           __nv_bfloat16* __restrict__ Thi,
                           __nv_bfloat16* __restrict__ Tlo) {
    __shared__ float t[32][33];
    const int z = blockIdx.z;
    const float* W = (z == 0) ? W0 : (z == 1) ? W1 : (z == 2) ? W2 : W3;
    __nv_bfloat16* th = Thi + (size_t)z * 1048576;
    __nv_bfloat16* tl = Tlo + (size_t)z * 1048576;
    int kb = blockIdx.x * 32, nb = blockIdx.y * 32;
    int x = threadIdx.x, y = threadIdx.y;  // 32 x 8
    #pragma unroll
    for (int i = 0; i < 32; i += 8)
        t[y + i][x] = W[(size_t)(kb + y + i) * 1024 + nb + x];
    __syncthreads();
    #pragma unroll
    for (int i = 0; i < 32; i += 8) {
        float v = t[x][y + i];
        int n = nb + y + i, k = kb + x;
        __nv_bfloat16 h, l; split_bf16(v, h, l);
        th[(size_t)n * 1024 + k] = h;
        tl[(size_t)n * 1024 + k] = l;
    }
}

__global__ void bias_concat(const float* __restrict__ bq, const float* __restrict__ bk,
                            const float* __restrict__ bv, float* __restrict__ dst) {
    int idx = blockIdx.x * 256 + threadIdx.x;  // 3072
    int which = idx >> 10, j = idx & 1023;
    dst[idx] = (which == 0) ? bq[j] : (which == 1) ? bk[j] : bv[j];
}

// ======================= mma.sync split-bf16 GEMM ===========================
// C = A[M,K] @ B^T (B stored [N,K]). 3-term bf16 split, CTA 128x128, BK=32,
// 3-stage cp.async. mode 0: fp32 row-major. mode 1: fp32 head layout.
// mode 2: bf16 hi/lo. mode 3: fused-qkv head layout (N=3072; C/C2/C3).
__global__ void __launch_bounds__(256, 2) tc_gemm(
    const __nv_bfloat16* __restrict__ Ahi, const __nv_bfloat16* __restrict__ Alo,
    const __nv_bfloat16* __restrict__ Bhi, const __nv_bfloat16* __restrict__ Blo,
    const float* __restrict__ bias, float* __restrict__ C,
    float* __restrict__ C2, float* __restrict__ C3,
    __nv_bfloat16* __restrict__ Chi, __nv_bfloat16* __restrict__ Clo,
    int M, int N, int K, int mode)
{
    extern __shared__ char smem[];
    const uint32_t sb = smem_u32(smem);
    const int tid = threadIdx.x, wid = tid >> 5, lane = tid & 31;
    const int m0 = blockIdx.y * 128, n0 = blockIdx.x * 128;

    const uint32_t STG = 32768;

    const int row0 = tid >> 2;
    const int row1 = row0 + 64;
    const int seg = tid & 3;
    const uint32_t soff0 = swz64(row0 * 64 + seg * 16);
    const uint32_t soff1 = swz64(row1 * 64 + seg * 16);

    const __nv_bfloat16* Ah_g = Ahi + (size_t)(m0 + row0) * K + seg * 8;
    const __nv_bfloat16* Al_g = Alo + (size_t)(m0 + row0) * K + seg * 8;
    const __nv_bfloat16* Bh_g = Bhi + (size_t)(n0 + row0) * K + seg * 8;
    const __nv_bfloat16* Bl_g = Blo + (size_t)(n0 + row0) * K + seg * 8;
    const size_t rstep = (size_t)64 * K;

    const int NK = K >> 5;

    auto issue_stage = [&](int kt) {
        const uint32_t s = sb + (kt % 3) * STG;
        const size_t ko = (size_t)kt * 32;
        cp_async16(s + soff0,         Ah_g + ko);
        cp_async16(s + soff1,         Ah_g + ko + rstep);
        cp_async16(s + 8192  + soff0, Al_g + ko);
        cp_async16(s + 8192  + soff1, Al_g + ko + rstep);
        cp_async16(s + 16384 + soff0, Bh_g + ko);
        cp_async16(s + 16384 + soff1, Bh_g + ko + rstep);
        cp_async16(s + 24576 + soff0, Bl_g + ko);
        cp_async16(s + 24576 + soff1, Bl_g + ko + rstep);
    };

    issue_stage(0); cp_commit();
    issue_stage(1); cp_commit();

    const int wm = (wid & 3) * 32;
    const int wn = (wid >> 2) * 64;
    const int a_row = wm + (lane & 15);
    const int a_kb = (lane >> 4) * 16;
    const int b_row = wn + (lane & 7) + ((lane >> 4) & 1) * 8;
    const int b_kb = ((lane >> 3) & 1) * 16;

    float4 acc[2][8];
    #pragma unroll
    for (int i = 0; i < 2; i++)
        #pragma unroll
        for (int j = 0; j < 8; j++) acc[i][j] = make_float4(0.f, 0.f, 0.f, 0.f);

    for (int kt = 0; kt < NK; kt++) {
        cp_wait1();
        __syncthreads();
        if (kt + 2 < NK) issue_stage(kt + 2);
        cp_commit();

        const uint32_t s = sb + (kt % 3) * STG;
        #pragma unroll
        for (int kb = 0; kb < 2; kb++) {
            uint32_t ah[2][4], al[2][4];
            #pragma unroll
            for (int mi = 0; mi < 2; mi++) {
                uint32_t off = swz64((a_row + mi * 16) * 64 + kb * 32 + a_kb);
                ldsm_x4(ah[mi], s + off);
                ldsm_x4(al[mi], s + 8192 + off);
            }
            #pragma unroll
            for (int g = 0; g < 4; g++) {
                uint32_t bh[4], bl[4];
                uint32_t off = swz64((b_row + g * 16) * 64 + kb * 32 + b_kb);
                ldsm_x4(bh, s + 16384 + off);
                ldsm_x4(bl, s + 24576 + off);
                #pragma unroll
                for (int mi = 0; mi < 2; mi++) {
                    mma_bf16(acc[mi][2 * g],     ah[mi], bh[0], bh[1]);
                    mma_bf16(acc[mi][2 * g + 1], ah[mi], bh[2], bh[3]);
                    mma_bf16(acc[mi][2 * g],     ah[mi], bl[0], bl[1]);
                    mma_bf16(acc[mi][2 * g + 1], ah[mi], bl[2], bl[3]);
                    mma_bf16(acc[mi][2 * g],     al[mi], bh[0], bh[1]);
                    mma_bf16(acc[mi][2 * g + 1], al[mi], bh[2], bh[3]);
                }
            }
        }
        __syncthreads();
    }

    // ---- epilogue ----
    #pragma unroll
    for (int mi = 0; mi < 2; mi++) {
        const int ra = m0 + wm + mi * 16 + (lane >> 2);
        const int rb = ra + 8;
        #pragma unroll
        for (int ni = 0; ni < 8; ni++) {
            const int c = n0 + wn + ni * 8 + (lane & 3) * 2;
            const float bx = bias[c], by = bias[c + 1];
            float4 v = acc[mi][ni];
            v.x += bx; v.y += by; v.z += bx; v.w += by;
            if (mode == 0) {
                *(float2*)&C[(size_t)ra * N + c] = make_float2(v.x, v.y);
                *(float2*)&C[(size_t)rb * N + c] = make_float2(v.z, v.w);
            } else if (mode == 1 || mode == 3) {
                float* base = C;
                int cc = c;
                if (mode == 3) {
                    int which = c >> 10;
                    cc = c & 1023;
                    base = (which == 0) ? C : (which == 1) ? C2 : C3;
                }
                const int h = cc >> 7, d = cc & 127;
                const int ba_ = ra >> 8, ta = ra & 255;
                const int bb_ = rb >> 8, tb = rb & 255;
                float* pa = base + (((size_t)(ba_ * 8 + h) * 256 + ta) * 128 + d);
                float* pb = base + (((size_t)(bb_ * 8 + h) * 256 + tb) * 128 + d);
                *(float2*)pa = make_float2(v.x, v.y);
                *(float2*)pb = make_float2(v.z, v.w);
            } else {
                uint32_t h0, l0, h1, l1;
                split_pack2(v.x, v.y, h0, l0);
                split_pack2(v.z, v.w, h1, l1);
                *(uint32_t*)&Chi[(size_t)ra * N + c] = h0;
                *(uint32_t*)&Clo[(size_t)ra * N + c] = l0;
                *(uint32_t*)&Chi[(size_t)rb * N + c] = h1;
                *(uint32_t*)&Clo[(size_t)rb * N + c] = l1;
            }
        }
    }
}

// ======================= tensor-core causal attention =======================
// grid (512 bh, 4 qtiles), 128 threads (4 warps). Warp w owns q rows w*16..+15.
// Q/K/V fp32 [BH,256,128] -> split bf16 in smem (stride 136 = conflict-free
// ldmatrix). S = QK^T and O += P V via m16n8k16, 3-term split each.
__global__ void __launch_bounds__(128) attn_mma(
    const float* __restrict__ Q, const float* __restrict__ Kp,
    const float* __restrict__ Vp,
    __nv_bfloat16* __restrict__ Yhi, __nv_bfloat16* __restrict__ Ylo)
{
    extern __shared__ char smraw[];
    const uint32_t SQH = 0, SQL = 17408, SKH = 2 * 17408, SKL = 3 * 17408,
                   SVH = 4 * 17408, SVL = 5 * 17408;   // 64*136*2 each
    const uint32_t sb = smem_u32(smraw);

    const int bh = blockIdx.x, qt = blockIdx.y;
    const int tid = threadIdx.x, wid = tid >> 5, lane = tid & 31;
    const float scale = 0.08838834764831845f;  // 1/sqrt(128)

    // ---- load Q (scaled, split) ----
    const float* qg = Q + ((size_t)bh * 256 + qt * 64) * 128;
    for (int i = tid; i < 2048; i += 128) {
        int row = i >> 5, c4 = (i & 31) * 4;
        float4 v = *(const float4*)(qg + (size_t)row * 128 + c4);
        v.x *= scale; v.y *= scale; v.z *= scale; v.w *= scale;
        uint32_t h0, l0, h1, l1;
        split_pack2(v.x, v.y, h0, l0);
        split_pack2(v.z, v.w, h1, l1);
        uint32_t off = (row * 136 + c4) * 2;
        *(uint2*)(smraw + SQH + off) = make_uint2(h0, h1);
        *(uint2*)(smraw + SQL + off) = make_uint2(l0, l1);
    }

    float4 o_[16];
    #pragma unroll
    for (int i = 0; i < 16; i++) o_[i] = make_float4(0.f, 0.f, 0.f, 0.f);
    float m0 = -1e30f, m1 = -1e30f, l0_ = 0.f, l1_ = 0.f;

    const int qr = wid * 16;
    // ldmatrix lane addresses (element offsets within a [64][136] tile)
    const uint32_t a_off = ((qr + (lane & 15)) * 136 + (lane >> 4) * 8) * 2;
    const uint32_t bk_off = (((lane & 7) + ((lane >> 4) & 1) * 8) * 136 +
                             ((lane >> 3) & 1) * 8) * 2;
    const uint32_t bv_off = ((((lane >> 3) & 1) * 8 + (lane & 7)) * 136 +
                             (lane >> 4) * 8) * 2;

    for (int jt = 0; jt <= qt; jt++) {
        __syncthreads();
        // ---- load K, V tiles (split) ----
        const float* kg = Kp + ((size_t)bh * 256 + jt * 64) * 128;
        const float* vg = Vp + ((size_t)bh * 256 + jt * 64) * 128;
        for (int i = tid; i < 2048; i += 128) {
            int row = i >> 5, c4 = (i & 31) * 4;
            uint32_t off = (row * 136 + c4) * 2;
            float4 kv = *(const float4*)(kg + (size_t)row * 128 + c4);
            uint32_t h0, l0, h1, l1;
            split_pack2(kv.x, kv.y, h0, l0);
            split_pack2(kv.z, kv.w, h1, l1);
            *(uint2*)(smraw + SKH + off) = make_uint2(h0, h1);
            *(uint2*)(smraw + SKL + off) = make_uint2(l0, l1);
            float4 vv = *(const float4*)(vg + (size_t)row * 128 + c4);
            split_pack2(vv.x, vv.y, h0, l0);
            split_pack2(vv.z, vv.w, h1, l1);
            *(uint2*)(smraw + SVH + off) = make_uint2(h0, h1);
            *(uint2*)(smraw + SVL + off) = make_uint2(l0, l1);
        }
        __syncthreads();

        // ---- S = Q K^T ----
        float4 s[8];
        #pragma unroll
        for (int n = 0; n < 8; n++) s[n] = make_float4(0.f, 0.f, 0.f, 0.f);
        #pragma unroll
        for (int dk = 0; dk < 8; dk++) {
            uint32_t ah[4], al[4];
            ldsm_x4(ah, sb + SQH + a_off + dk * 32);
            ldsm_x4(al, sb + SQL + a_off + dk * 32);
            #pragma unroll
            for (int np = 0; np < 4; np++) {
                uint32_t kh[4], kl[4];
                uint32_t off = bk_off + (np * 16 * 136 + dk * 16) * 2;
                ldsm_x4(kh, sb + SKH + off);
                ldsm_x4(kl, sb + SKL + off);
                mma_bf16(s[2 * np],     ah, kh[0], kh[1]);
                mma_bf16(s[2 * np + 1], ah, kh[2], kh[3]);
                mma_bf16(s[2 * np],     ah, kl[0], kl[1]);
                mma_bf16(s[2 * np + 1], ah, kl[2], kl[3]);
                mma_bf16(s[2 * np],     al, kh[0], kh[1]);
                mma_bf16(s[2 * np + 1], al, kh[2], kh[3]);
            }
        }

        // ---- causal mask on diagonal tile ----
        if (jt == qt) {
            const int r0 = qr + (lane >> 2), r1 = r0 + 8;
            #pragma unroll
            for (int n = 0; n < 8; n++) {
                int c = n * 8 + (lane & 3) * 2;
                if (c > r0) s[n].x = -1e30f;
                if (c + 1 > r0) s[n].y = -1e30f;
                if (c > r1) s[n].z = -1e30f;
                if (c + 1 > r1) s[n].w = -1e30f;
            }
        }

        // ---- online softmax ----
        float mx0 = -1e30f, mx1 = -1e30f;
        #pragma unroll
        for (int n = 0; n < 8; n++) {
            mx0 = fmaxf(mx0, fmaxf(s[n].x, s[n].y));
            mx1 = fmaxf(mx1, fmaxf(s[n].z, s[n].w));
        }
        mx0 = fmaxf(mx0, __shfl_xor_sync(0xffffffffu, mx0, 1));
        mx0 = fmaxf(mx0, __shfl_xor_sync(0xffffffffu, mx0, 2));
        mx1 = fmaxf(mx1, __shfl_xor_sync(0xffffffffu, mx1, 1));
        mx1 = fmaxf(mx1, __shfl_xor_sync(0xffffffffu, mx1, 2));
        const float mn0 = fmaxf(m0, mx0), mn1 = fmaxf(m1, mx1);
        const float al0 = __expf(m0 - mn0), al1 = __expf(m1 - mn1);
        float sum0 = 0.f, sum1 = 0.f;
        #pragma unroll
        for (int n = 0; n < 8; n++) {
            s[n].x = __expf(s[n].x - mn0); sum0 += s[n].x;
            s[n].y = __expf(s[n].y - mn0); sum0 += s[n].y;
            s[n].z = __expf(s[n].z - mn1); sum1 += s[n].z;
            s[n].w = __expf(s[n].w - mn1); sum1 += s[n].w;
        }
        sum0 += __shfl_xor_sync(0xffffffffu, sum0, 1);
        sum0 += __shfl_xor_sync(0xffffffffu, sum0, 2);
        sum1 += __shfl_xor_sync(0xffffffffu, sum1, 1);
        sum1 += __shfl_xor_sync(0xffffffffu, sum1, 2);
        l0_ = l0_ * al0 + sum0;
        l1_ = l1_ * al1 + sum1;
        m0 = mn0; m1 = mn1;
        #pragma unroll
        for (int i = 0; i < 16; i++) {
            o_[i].x *= al0; o_[i].y *= al0;
            o_[i].z *= al1; o_[i].w *= al1;
        }

        // ---- O += P V ----
        #pragma unroll
        for (int kc = 0; kc < 4; kc++) {
            uint32_t pah[4], pal[4];
            split_pack2(s[2 * kc].x,     s[2 * kc].y,     pah[0], pal[0]);
            split_pack2(s[2 * kc].z,     s[2 * kc].w,     pah[1], pal[1]);
            split_pack2(s[2 * kc + 1].x, s[2 * kc + 1].y, pah[2], pal[2]);
            split_pack2(s[2 * kc + 1].z, s[2 * kc + 1].w, pah[3], pal[3]);
            #pragma unroll
            for (int nd = 0; nd < 8; nd++) {
                uint32_t vh[4], vl[4];
                uint32_t off = bv_off + (kc * 16 * 136 + nd * 16) * 2;
                ldsm_x4_t(vh, sb + SVH + off);
                ldsm_x4_t(vl, sb + SVL + off);
                mma_bf16(o_[2 * nd],     pah, vh[0], vh[1]);
                mma_bf16(o_[2 * nd + 1], pah, vh[2], vh[3]);
                mma_bf16(o_[2 * nd],     pah, vl[0], vl[1]);
                mma_bf16(o_[2 * nd + 1], pah, vl[2], vl[3]);
                mma_bf16(o_[2 * nd],     pal, vh[0], vh[1]);
                mma_bf16(o_[2 * nd + 1], pal, vh[2], vh[3]);
            }
        }
    }

    // ---- write output (split bf16, [B,T,C] layout) ----
    const float inv0 = 1.0f / l0_, inv1 = 1.0f / l1_;
    const int b = bh >> 3, h = bh & 7;
    const int t0 = qt * 64 + qr + (lane >> 2), t1 = t0 + 8;
    const size_t base0 = ((size_t)(b * 256 + t0)) * 1024 + h * 128;
    const size_t base1 = ((size_t)(b * 256 + t1)) * 1024 + h * 128;
    #pragma unroll
    for (int nd = 0; nd < 16; nd++) {
        const int c = nd * 8 + (lane & 3) * 2;
        uint32_t h0, l0, h1, l1;
        split_pack2(o_[nd].x * inv0, o_[nd].y * inv0, h0, l0);
        split_pack2(o_[nd].z * inv1, o_[nd].w * inv1, h1, l1);
        *(uint32_t*)&Yhi[base0 + c] = h0;
        *(uint32_t*)&Ylo[base0 + c] = l0;
        *(uint32_t*)&Yhi[base1 + c] = h1;
        *(uint32_t*)&Ylo[base1 + c] = l1;
    }
}

// ======================= launcher ===========================================
extern "C" void kernel_launch(void* const* d_in, const int* in_sizes, int n_in,
                              void* d_out, int out_size) {
    const float* x      = (const float*)d_in[0];
    const float* conv_w = (const float*)d_in[1];
    const float* conv_b = (const float*)d_in[2];
    const float* Wq     = (const float*)d_in[3];
    const float* bq     = (const float*)d_in[4];
    const float* Wk     = (const float*)d_in[5];
    const float* bk     = (const float*)d_in[6];
    const float* Wv     = (const float*)d_in[7];
    const float* bv     = (const float*)d_in[8];
    const float* Wp     = (const float*)d_in[9];
    const float* bp     = (const float*)d_in[10];
    float* out = (float*)d_out;

    const size_t YN = (size_t)64 * 256 * 1024;
    float* kout = out + YN;
    float* vout = out + 2 * YN;

    __nv_bfloat16 *phi, *plo, *wchi, *wclo, *wthi, *wtlo, *tokhi, *toklo, *yhi, *ylo;
    float *q, *bqkv;
    cudaGetSymbolAddress((void**)&phi, g_phi);
    cudaGetSymbolAddress((void**)&plo, g_plo);
    cudaGetSymbolAddress((void**)&wchi, g_wchi);
    cudaGetSymbolAddress((void**)&wclo, g_wclo);
    cudaGetSymbolAddress((void**)&wthi, g_wthi);
    cudaGetSymbolAddress((void**)&wtlo, g_wtlo);
    cudaGetSymbolAddress((void**)&tokhi, g_tokhi);
    cudaGetSymbolAddress((void**)&toklo, g_toklo);
    cudaGetSymbolAddress((void**)&q, g_q);
    cudaGetSymbolAddress((void**)&yhi, g_yhi);
    cudaGetSymbolAddress((void**)&ylo, g_ylo);
    cudaGetSymbolAddress((void**)&bqkv, g_bqkv);

    const int GEMM_SMEM = 3 * 32768;
    cudaFuncSetAttribute(tc_gemm, cudaFuncAttributeMaxDynamicSharedMemorySize,
                         GEMM_SMEM);
    const int ATTN_SMEM = 6 * 64 * 136 * 2;   // 104448
    cudaFuncSetAttribute(attn_mma, cudaFuncAttributeMaxDynamicSharedMemorySize,
                         ATTN_SMEM);

    // prep (1..4)
    im2col_split<<<16384, 256>>>(x, phi, plo);
    split_elem<<<1024, 256>>>(conv_w, wchi, wclo);
    wtrans_all<<<dim3(32, 32, 4), dim3(32, 8)>>>(Wq, Wk, Wv, Wp, wthi, wtlo);
    bias_concat<<<12, 256>>>(bq, bk, bv, bqkv);

    // (5) tok = patches @ conv_w^T + conv_b
    tc_gemm<<<dim3(8, 128), 256, GEMM_SMEM>>>(phi, plo, wchi, wclo, conv_b,
                                              nullptr, nullptr, nullptr,
                                              tokhi, toklo, 16384, 1024, 256, 2);
    // (6) fused qkv  [profiled launch]
    tc_gemm<<<dim3(24, 128), 256, GEMM_SMEM>>>(tokhi, toklo, wthi, wtlo, bqkv,
                                               q, kout, vout, nullptr, nullptr,
                                               16384, 3072, 1024, 3);
    // (7) attention
    attn_mma<<<dim3(512, 4), 128, ATTN_SMEM>>>(q, kout, vout, yhi, ylo);
    // (8) y = yh @ Wp^T + bp
    tc_gemm<<<dim3(8, 128), 256, GEMM_SMEM>>>(yhi, ylo, wthi + 3 * 1048576,
                                              wtlo + 3 * 1048576, bp, out,
                                              nullptr, nullptr, nullptr, nullptr,
                                              16384, 1024, 1024, 0);
}

// round 5
// speedup vs baseline: 2.6065x; 1.0116x over previous
#include <cuda_runtime.h>
#include <cuda_bf16.h>
#include <cstdint>

// ======================= scratch (device globals) ==========================
__device__ __nv_bfloat16 g_phi[16384 * 256];
__device__ __nv_bfloat16 g_plo[16384 * 256];
__device__ __nv_bfloat16 g_wchi[1024 * 256];
__device__ __nv_bfloat16 g_wclo[1024 * 256];
__device__ __nv_bfloat16 g_wthi[4 * 1024 * 1024]; // Wq,Wk,Wv,Wp [N,K] K-major
__device__ __nv_bfloat16 g_wtlo[4 * 1024 * 1024];
__device__ __nv_bfloat16 g_tokhi[16384 * 1024];
__device__ __nv_bfloat16 g_toklo[16384 * 1024];
__device__ __nv_bfloat16 g_qhi[16384 * 1024];     // q scaled, split, [B,H,T,D]
__device__ __nv_bfloat16 g_qlo[16384 * 1024];
__device__ __nv_bfloat16 g_yhi[16384 * 1024];     // attn out hi [B,T,C]
__device__ __nv_bfloat16 g_ylo[16384 * 1024];
__device__ float         g_bqkv[3072];

// ======================= small helpers ======================================
__device__ __forceinline__ uint32_t smem_u32(const void* p) {
    uint32_t a;
    asm("{ .reg .u64 t; cvta.to.shared.u64 t, %1; cvt.u32.u64 %0, t; }"
        : "=r"(a) : "l"(p));
    return a;
}
__device__ __forceinline__ void cp_async16(uint32_t saddr, const void* gaddr) {
    asm volatile("cp.async.cg.shared.global [%0], [%1], 16;"
                 :: "r"(saddr), "l"(gaddr));
}
__device__ __forceinline__ void cp_commit() {
    asm volatile("cp.async.commit_group;");
}
__device__ __forceinline__ void cp_wait1() {
    asm volatile("cp.async.wait_group 1;");
}
__device__ __forceinline__ void ldsm_x4(uint32_t* r, uint32_t addr) {
    asm volatile("ldmatrix.sync.aligned.m8n8.x4.shared.b16 {%0,%1,%2,%3}, [%4];"
                 : "=r"(r[0]), "=r"(r[1]), "=r"(r[2]), "=r"(r[3]) : "r"(addr));
}
__device__ __forceinline__ void ldsm_x4_t(uint32_t* r, uint32_t addr) {
    asm volatile("ldmatrix.sync.aligned.m8n8.x4.trans.shared.b16 {%0,%1,%2,%3}, [%4];"
                 : "=r"(r[0]), "=r"(r[1]), "=r"(r[2]), "=r"(r[3]) : "r"(addr));
}
__device__ __forceinline__ void mma_bf16(float4& d, const uint32_t a[4],
                                         uint32_t b0, uint32_t b1) {
    asm volatile(
        "mma.sync.aligned.m16n8k16.row.col.f32.bf16.bf16.f32 "
        "{%0,%1,%2,%3}, {%4,%5,%6,%7}, {%8,%9}, {%0,%1,%2,%3};"
        : "+f"(d.x), "+f"(d.y), "+f"(d.z), "+f"(d.w)
        : "r"(a[0]), "r"(a[1]), "r"(a[2]), "r"(a[3]), "r"(b0), "r"(b1));
}
__device__ __forceinline__ uint32_t swz64(uint32_t x) {
    return x ^ ((x >> 3) & 0x30);
}
__device__ __forceinline__ void split_bf16(float v, __nv_bfloat16& hi, __nv_bfloat16& lo) {
    hi = __float2bfloat16(v);
    lo = __float2bfloat16(v - __bfloat162float(hi));
}
// split a float pair into packed-hi / packed-lo halves
__device__ __forceinline__ void split_pack2(float a, float b,
                                            uint32_t& hi, uint32_t& lo) {
    __nv_bfloat16 ha, la, hb, lb;
    split_bf16(a, ha, la);
    split_bf16(b, hb, lb);
    __nv_bfloat162 ph = __nv_bfloat162(ha, hb);
    __nv_bfloat162 pl = __nv_bfloat162(la, lb);
    hi = *reinterpret_cast<uint32_t*>(&ph);
    lo = *reinterpret_cast<uint32_t*>(&pl);
}

// ======================= prep kernels =======================================
__global__ void im2col_split(const float* __restrict__ x,
                             __nv_bfloat16* __restrict__ Phi,
                             __nv_bfloat16* __restrict__ Plo) {
    int idx = blockIdx.x * 256 + threadIdx.x;
    int p = idx & 255, r = idx >> 8;
    int px = p & 15, py = p >> 4;
    int t = r & 255, b = r >> 8;
    int tx = t & 15, ty = t >> 4;
    float v = x[(size_t)b * 65536 + (size_t)(ty * 16 + py) * 256 + tx * 16 + px];
    __nv_bfloat16 h, l; split_bf16(v, h, l);
    Phi[idx] = h; Plo[idx] = l;
}

__global__ void split_elem(const float* __restrict__ W,
                           __nv_bfloat16* __restrict__ H,
                           __nv_bfloat16* __restrict__ L) {
    int idx = blockIdx.x * 256 + threadIdx.x;
    __nv_bfloat16 h, l; split_bf16(W[idx], h, l);
    H[idx] = h; L[idx] = l;
}

__global__ void wtrans_all(const float* __restrict__ W0, const float* __restrict__ W1,
                           const float* __restrict__ W2, const float* __restrict__ W3,
                           __nv_bfloat16* __restrict__ Thi,
                           __nv_bfloat16* __restrict__ Tlo) {
    __shared__ float t[32][33];
    const int z = blockIdx.z;
    const float* W = (z == 0) ? W0 : (z == 1) ? W1 : (z == 2) ? W2 : W3;
    __nv_bfloat16* th = Thi + (size_t)z * 1048576;
    __nv_bfloat16* tl = Tlo + (size_t)z * 1048576;
    int kb = blockIdx.x * 32, nb = blockIdx.y * 32;
    int x = threadIdx.x, y = threadIdx.y;  // 32 x 8
    #pragma unroll
    for (int i = 0; i < 32; i += 8)
        t[y + i][x] = W[(size_t)(kb + y + i) * 1024 + nb + x];
    __syncthreads();
    #pragma unroll
    for (int i = 0; i < 32; i += 8) {
        float v = t[x][y + i];
        int n = nb + y + i, k = kb + x;
        __nv_bfloat16 h, l; split_bf16(v, h, l);
        th[(size_t)n * 1024 + k] = h;
        tl[(size_t)n * 1024 + k] = l;
    }
}

__global__ void bias_concat(const float* __restrict__ bq, const float* __restrict__ bk,
                            const float* __restrict__ bv, float* __restrict__ dst) {
    int idx = blockIdx.x * 256 + threadIdx.x;  // 3072
    int which = idx >> 10, j = idx & 1023;
    dst[idx] = (which == 0) ? bq[j] : (which == 1) ? bk[j] : bv[j];
}

// ======================= mma.sync split-bf16 GEMM ===========================
// C = A[M,K] @ B^T (B stored [N,K]). 3-term bf16 split, CTA 128x128, BK=32,
// 3-stage cp.async. mode 0: fp32 row-major. mode 2: bf16 hi/lo row-major.
// mode 3: fused-qkv: q -> scaled split bf16 head layout (Chi/Clo),
//                    k -> fp32 head layout (C), v -> fp32 head layout (C2).
__global__ void __launch_bounds__(256, 2) tc_gemm(
    const __nv_bfloat16* __restrict__ Ahi, const __nv_bfloat16* __restrict__ Alo,
    const __nv_bfloat16* __restrict__ Bhi, const __nv_bfloat16* __restrict__ Blo,
    const float* __restrict__ bias, float* __restrict__ C,
    float* __restrict__ C2,
    __nv_bfloat16* __restrict__ Chi, __nv_bfloat16* __restrict__ Clo,
    int M, int N, int K, int mode)
{
    extern __shared__ char smem[];
    const uint32_t sb = smem_u32(smem);
    const int tid = threadIdx.x, wid = tid >> 5, lane = tid & 31;
    const int m0 = blockIdx.y * 128, n0 = blockIdx.x * 128;

    const uint32_t STG = 32768;

    const int row0 = tid >> 2;
    const int row1 = row0 + 64;
    const int seg = tid & 3;
    const uint32_t soff0 = swz64(row0 * 64 + seg * 16);
    const uint32_t soff1 = swz64(row1 * 64 + seg * 16);

    const __nv_bfloat16* Ah_g = Ahi + (size_t)(m0 + row0) * K + seg * 8;
    const __nv_bfloat16* Al_g = Alo + (size_t)(m0 + row0) * K + seg * 8;
    const __nv_bfloat16* Bh_g = Bhi + (size_t)(n0 + row0) * K + seg * 8;
    const __nv_bfloat16* Bl_g = Blo + (size_t)(n0 + row0) * K + seg * 8;
    const size_t rstep = (size_t)64 * K;

    const int NK = K >> 5;

    auto issue_stage = [&](int kt) {
        const uint32_t s = sb + (kt % 3) * STG;
        const size_t ko = (size_t)kt * 32;
        cp_async16(s + soff0,         Ah_g + ko);
        cp_async16(s + soff1,         Ah_g + ko + rstep);
        cp_async16(s + 8192  + soff0, Al_g + ko);
        cp_async16(s + 8192  + soff1, Al_g + ko + rstep);
        cp_async16(s + 16384 + soff0, Bh_g + ko);
        cp_async16(s + 16384 + soff1, Bh_g + ko + rstep);
        cp_async16(s + 24576 + soff0, Bl_g + ko);
        cp_async16(s + 24576 + soff1, Bl_g + ko + rstep);
    };

    issue_stage(0); cp_commit();
    issue_stage(1); cp_commit();

    const int wm = (wid & 3) * 32;
    const int wn = (wid >> 2) * 64;
    const int a_row = wm + (lane & 15);
    const int a_kb = (lane >> 4) * 16;
    const int b_row = wn + (lane & 7) + ((lane >> 4) & 1) * 8;
    const int b_kb = ((lane >> 3) & 1) * 16;

    float4 acc[2][8];
    #pragma unroll
    for (int i = 0; i < 2; i++)
        #pragma unroll
        for (int j = 0; j < 8; j++) acc[i][j] = make_float4(0.f, 0.f, 0.f, 0.f);

    for (int kt = 0; kt < NK; kt++) {
        cp_wait1();
        __syncthreads();
        if (kt + 2 < NK) issue_stage(kt + 2);
        cp_commit();

        const uint32_t s = sb + (kt % 3) * STG;
        #pragma unroll
        for (int kb = 0; kb < 2; kb++) {
            uint32_t ah[2][4], al[2][4];
            #pragma unroll
            for (int mi = 0; mi < 2; mi++) {
                uint32_t off = swz64((a_row + mi * 16) * 64 + kb * 32 + a_kb);
                ldsm_x4(ah[mi], s + off);
                ldsm_x4(al[mi], s + 8192 + off);
            }
            // software-pipelined B fragments (double-buffered)
            uint32_t bh[2][4], bl[2][4];
            {
                uint32_t off = swz64(b_row * 64 + kb * 32 + b_kb);
                ldsm_x4(bh[0], s + 16384 + off);
                ldsm_x4(bl[0], s + 24576 + off);
            }
            #pragma unroll
            for (int g = 0; g < 4; g++) {
                const int cur = g & 1, nxt = cur ^ 1;
                if (g < 3) {
                    uint32_t off = swz64((b_row + (g + 1) * 16) * 64 + kb * 32 + b_kb);
                    ldsm_x4(bh[nxt], s + 16384 + off);
                    ldsm_x4(bl[nxt], s + 24576 + off);
                }
                #pragma unroll
                for (int mi = 0; mi < 2; mi++) {
                    mma_bf16(acc[mi][2 * g],     ah[mi], bh[cur][0], bh[cur][1]);
                    mma_bf16(acc[mi][2 * g + 1], ah[mi], bh[cur][2], bh[cur][3]);
                    mma_bf16(acc[mi][2 * g],     ah[mi], bl[cur][0], bl[cur][1]);
                    mma_bf16(acc[mi][2 * g + 1], ah[mi], bl[cur][2], bl[cur][3]);
                    mma_bf16(acc[mi][2 * g],     al[mi], bh[cur][0], bh[cur][1]);
                    mma_bf16(acc[mi][2 * g + 1], al[mi], bh[cur][2], bh[cur][3]);
                }
            }
        }
        __syncthreads();
    }

    // ---- epilogue ----
    const float qscale = 0.08838834764831845f;   // 1/sqrt(128)
    #pragma unroll
    for (int mi = 0; mi < 2; mi++) {
        const int ra = m0 + wm + mi * 16 + (lane >> 2);
        const int rb = ra + 8;
        #pragma unroll
        for (int ni = 0; ni < 8; ni++) {
            const int c = n0 + wn + ni * 8 + (lane & 3) * 2;
            const float bx = bias[c], by = bias[c + 1];
            float4 v = acc[mi][ni];
            v.x += bx; v.y += by; v.z += bx; v.w += by;
            if (mode == 0) {
                *(float2*)&C[(size_t)ra * N + c] = make_float2(v.x, v.y);
                *(float2*)&C[(size_t)rb * N + c] = make_float2(v.z, v.w);
            } else if (mode == 3) {
                const int which = c >> 10;
                const int cc = c & 1023;
                const int h = cc >> 7, d = cc & 127;
                const int ba_ = ra >> 8, ta = ra & 255;
                const int bb_ = rb >> 8, tb = rb & 255;
                const size_t oa = ((size_t)(ba_ * 8 + h) * 256 + ta) * 128 + d;
                const size_t ob = ((size_t)(bb_ * 8 + h) * 256 + tb) * 128 + d;
                if (which == 0) {
                    uint32_t h0, l0, h1, l1;
                    split_pack2(v.x * qscale, v.y * qscale, h0, l0);
                    split_pack2(v.z * qscale, v.w * qscale, h1, l1);
                    *(uint32_t*)&Chi[oa] = h0;
                    *(uint32_t*)&Clo[oa] = l0;
                    *(uint32_t*)&Chi[ob] = h1;
                    *(uint32_t*)&Clo[ob] = l1;
                } else {
                    float* base = (which == 1) ? C : C2;
                    *(float2*)&base[oa] = make_float2(v.x, v.y);
                    *(float2*)&base[ob] = make_float2(v.z, v.w);
                }
            } else {
                uint32_t h0, l0, h1, l1;
                split_pack2(v.x, v.y, h0, l0);
                split_pack2(v.z, v.w, h1, l1);
                *(uint32_t*)&Chi[(size_t)ra * N + c] = h0;
                *(uint32_t*)&Clo[(size_t)ra * N + c] = l0;
                *(uint32_t*)&Chi[(size_t)rb * N + c] = h1;
                *(uint32_t*)&Clo[(size_t)rb * N + c] = l1;
            }
        }
    }
}

// ======================= tensor-core causal attention =======================
// grid (512 bh, 4 qtiles), 128 threads (4 warps). Warp w owns q rows w*16..+15.
// Q pre-scaled split bf16 [BH,256,128]; K,V fp32 (present buffers).
__global__ void __launch_bounds__(128) attn_mma(
    const __nv_bfloat16* __restrict__ Qhi, const __nv_bfloat16* __restrict__ Qlo,
    const float* __restrict__ Kp, const float* __restrict__ Vp,
    __nv_bfloat16* __restrict__ Yhi, __nv_bfloat16* __restrict__ Ylo)
{
    extern __shared__ char smraw[];
    const uint32_t SQH = 0, SQL = 17408, SKH = 2 * 17408, SKL = 3 * 17408,
                   SVH = 4 * 17408, SVL = 5 * 17408;   // 64*136*2 each
    const uint32_t sb = smem_u32(smraw);

    const int bh = blockIdx.x, qt = blockIdx.y;
    const int tid = threadIdx.x, wid = tid >> 5, lane = tid & 31;

    // ---- load Q (already scaled + split): straight copy, stride 128 -> 136
    const __nv_bfloat16* qgh = Qhi + ((size_t)bh * 256 + qt * 64) * 128;
    const __nv_bfloat16* qgl = Qlo + ((size_t)bh * 256 + qt * 64) * 128;
    #pragma unroll
    for (int i = 0; i < 8; i++) {
        int e = tid + i * 128;        // 1024 segs of 8 bf16
        int row = e >> 4, sg = e & 15;
        uint4 vh = *(const uint4*)(qgh + (size_t)row * 128 + sg * 8);
        uint4 vl = *(const uint4*)(qgl + (size_t)row * 128 + sg * 8);
        uint32_t off = row * 272 + sg * 16;
        *(uint4*)(smraw + SQH + off) = vh;
        *(uint4*)(smraw + SQL + off) = vl;
    }

    float4 o_[16];
    #pragma unroll
    for (int i = 0; i < 16; i++) o_[i] = make_float4(0.f, 0.f, 0.f, 0.f);
    float m0 = -1e30f, m1 = -1e30f, l0_ = 0.f, l1_ = 0.f;

    const int qr = wid * 16;
    const uint32_t a_off = ((qr + (lane & 15)) * 136 + (lane >> 4) * 8) * 2;
    const uint32_t bk_off = (((lane & 7) + ((lane >> 4) & 1) * 8) * 136 +
                             ((lane >> 3) & 1) * 8) * 2;
    const uint32_t bv_off = ((((lane >> 3) & 1) * 8 + (lane & 7)) * 136 +
                             (lane >> 4) * 8) * 2;

    for (int jt = 0; jt <= qt; jt++) {
        __syncthreads();
        const float* kg = Kp + ((size_t)bh * 256 + jt * 64) * 128;
        const float* vg = Vp + ((size_t)bh * 256 + jt * 64) * 128;
        for (int i = tid; i < 2048; i += 128) {
            int row = i >> 5, c4 = (i & 31) * 4;
            uint32_t off = (row * 136 + c4) * 2;
            float4 kv = *(const float4*)(kg + (size_t)row * 128 + c4);
            uint32_t h0, l0, h1, l1;
            split_pack2(kv.x, kv.y, h0, l0);
            split_pack2(kv.z, kv.w, h1, l1);
            *(uint2*)(smraw + SKH + off) = make_uint2(h0, h1);
            *(uint2*)(smraw + SKL + off) = make_uint2(l0, l1);
            float4 vv = *(const float4*)(vg + (size_t)row * 128 + c4);
            split_pack2(vv.x, vv.y, h0, l0);
            split_pack2(vv.z, vv.w, h1, l1);
            *(uint2*)(smraw + SVH + off) = make_uint2(h0, h1);
            *(uint2*)(smraw + SVL + off) = make_uint2(l0, l1);
        }
        __syncthreads();

        // ---- S = Q K^T ----
        float4 s[8];
        #pragma unroll
        for (int n = 0; n < 8; n++) s[n] = make_float4(0.f, 0.f, 0.f, 0.f);
        #pragma unroll
        for (int dk = 0; dk < 8; dk++) {
            uint32_t ah[4], al[4];
            ldsm_x4(ah, sb + SQH + a_off + dk * 32);
            ldsm_x4(al, sb + SQL + a_off + dk * 32);
            #pragma unroll
            for (int np = 0; np < 4; np++) {
                uint32_t kh[4], kl[4];
                uint32_t off = bk_off + (np * 16 * 136 + dk * 16) * 2;
                ldsm_x4(kh, sb + SKH + off);
                ldsm_x4(kl, sb + SKL + off);
                mma_bf16(s[2 * np],     ah, kh[0], kh[1]);
                mma_bf16(s[2 * np + 1], ah, kh[2], kh[3]);
                mma_bf16(s[2 * np],     ah, kl[0], kl[1]);
                mma_bf16(s[2 * np + 1], ah, kl[2], kl[3]);
                mma_bf16(s[2 * np],     al, kh[0], kh[1]);
                mma_bf16(s[2 * np + 1], al, kh[2], kh[3]);
            }
        }

        if (jt == qt) {
            const int r0 = qr + (lane >> 2), r1 = r0 + 8;
            #pragma unroll
            for (int n = 0; n < 8; n++) {
                int c = n * 8 + (lane & 3) * 2;
                if (c > r0) s[n].x = -1e30f;
                if (c + 1 > r0) s[n].y = -1e30f;
                if (c > r1) s[n].z = -1e30f;
                if (c + 1 > r1) s[n].w = -1e30f;
            }
        }

        // ---- online softmax ----
        float mx0 = -1e30f, mx1 = -1e30f;
        #pragma unroll
        for (int n = 0; n < 8; n++) {
            mx0 = fmaxf(mx0, fmaxf(s[n].x, s[n].y));
            mx1 = fmaxf(mx1, fmaxf(s[n].z, s[n].w));
        }
        mx0 = fmaxf(mx0, __shfl_xor_sync(0xffffffffu, mx0, 1));
        mx0 = fmaxf(mx0, __shfl_xor_sync(0xffffffffu, mx0, 2));
        mx1 = fmaxf(mx1, __shfl_xor_sync(0xffffffffu, mx1, 1));
        mx1 = fmaxf(mx1, __shfl_xor_sync(0xffffffffu, mx1, 2));
        const float mn0 = fmaxf(m0, mx0), mn1 = fmaxf(m1, mx1);
        const float al0 = __expf(m0 - mn0), al1 = __expf(m1 - mn1);
        float sum0 = 0.f, sum1 = 0.f;
        #pragma unroll
        for (int n = 0; n < 8; n++) {
            s[n].x = __expf(s[n].x - mn0); sum0 += s[n].x;
            s[n].y = __expf(s[n].y - mn0); sum0 += s[n].y;
            s[n].z = __expf(s[n].z - mn1); sum1 += s[n].z;
            s[n].w = __expf(s[n].w - mn1); sum1 += s[n].w;
        }
        sum0 += __shfl_xor_sync(0xffffffffu, sum0, 1);
        sum0 += __shfl_xor_sync(0xffffffffu, sum0, 2);
        sum1 += __shfl_xor_sync(0xffffffffu, sum1, 1);
        sum1 += __shfl_xor_sync(0xffffffffu, sum1, 2);
        l0_ = l0_ * al0 + sum0;
        l1_ = l1_ * al1 + sum1;
        m0 = mn0; m1 = mn1;
        #pragma unroll
        for (int i = 0; i < 16; i++) {
            o_[i].x *= al0; o_[i].y *= al0;
            o_[i].z *= al1; o_[i].w *= al1;
        }

        // ---- O += P V ----
        #pragma unroll
        for (int kc = 0; kc < 4; kc++) {
            uint32_t pah[4], pal[4];
            split_pack2(s[2 * kc].x,     s[2 * kc].y,     pah[0], pal[0]);
            split_pack2(s[2 * kc].z,     s[2 * kc].w,     pah[1], pal[1]);
            split_pack2(s[2 * kc + 1].x, s[2 * kc + 1].y, pah[2], pal[2]);
            split_pack2(s[2 * kc + 1].z, s[2 * kc + 1].w, pah[3], pal[3]);
            #pragma unroll
            for (int nd = 0; nd < 8; nd++) {
                uint32_t vh[4], vl[4];
                uint32_t off = bv_off + (kc * 16 * 136 + nd * 16) * 2;
                ldsm_x4_t(vh, sb + SVH + off);
                ldsm_x4_t(vl, sb + SVL + off);
                mma_bf16(o_[2 * nd],     pah, vh[0], vh[1]);
                mma_bf16(o_[2 * nd + 1], pah, vh[2], vh[3]);
                mma_bf16(o_[2 * nd],     pah, vl[0], vl[1]);
                mma_bf16(o_[2 * nd + 1], pah, vl[2], vl[3]);
                mma_bf16(o_[2 * nd],     pal, vh[0], vh[1]);
                mma_bf16(o_[2 * nd + 1], pal, vh[2], vh[3]);
            }
        }
    }

    // ---- write output (split bf16, [B,T,C] layout) ----
    const float inv0 = 1.0f / l0_, inv1 = 1.0f / l1_;
    const int b = bh >> 3, h = bh & 7;
    const int t0 = qt * 64 + qr + (lane >> 2), t1 = t0 + 8;
    const size_t base0 = ((size_t)(b * 256 + t0)) * 1024 + h * 128;
    const size_t base1 = ((size_t)(b * 256 + t1)) * 1024 + h * 128;
    #pragma unroll
    for (int nd = 0; nd < 16; nd++) {
        const int c = nd * 8 + (lane & 3) * 2;
        uint32_t h0, l0, h1, l1;
        split_pack2(o_[nd].x * inv0, o_[nd].y * inv0, h0, l0);
        split_pack2(o_[nd].z * inv1, o_[nd].w * inv1, h1, l1);
        *(uint32_t*)&Yhi[base0 + c] = h0;
        *(uint32_t*)&Ylo[base0 + c] = l0;
        *(uint32_t*)&Yhi[base1 + c] = h1;
        *(uint32_t*)&Ylo[base1 + c] = l1;
    }
}

// ======================= launcher ===========================================
extern "C" void kernel_launch(void* const* d_in, const int* in_sizes, int n_in,
                              void* d_out, int out_size) {
    const float* x      = (const float*)d_in[0];
    const float* conv_w = (const float*)d_in[1];
    const float* conv_b = (const float*)d_in[2];
    const float* Wq     = (const float*)d_in[3];
    const float* bq     = (const float*)d_in[4];
    const float* Wk     = (const float*)d_in[5];
    const float* bk     = (const float*)d_in[6];
    const float* Wv     = (const float*)d_in[7];
    const float* bv     = (const float*)d_in[8];
    const float* Wp     = (const float*)d_in[9];
    const float* bp     = (const float*)d_in[10];
    float* out = (float*)d_out;

    const size_t YN = (size_t)64 * 256 * 1024;
    float* kout = out + YN;
    float* vout = out + 2 * YN;

    __nv_bfloat16 *phi, *plo, *wchi, *wclo, *wthi, *wtlo, *tokhi, *toklo;
    __nv_bfloat16 *qhi, *qlo, *yhi, *ylo;
    float* bqkv;
    cudaGetSymbolAddress((void**)&phi, g_phi);
    cudaGetSymbolAddress((void**)&plo, g_plo);
    cudaGetSymbolAddress((void**)&wchi, g_wchi);
    cudaGetSymbolAddress((void**)&wclo, g_wclo);
    cudaGetSymbolAddress((void**)&wthi, g_wthi);
    cudaGetSymbolAddress((void**)&wtlo, g_wtlo);
    cudaGetSymbolAddress((void**)&tokhi, g_tokhi);
    cudaGetSymbolAddress((void**)&toklo, g_toklo);
    cudaGetSymbolAddress((void**)&qhi, g_qhi);
    cudaGetSymbolAddress((void**)&qlo, g_qlo);
    cudaGetSymbolAddress((void**)&yhi, g_yhi);
    cudaGetSymbolAddress((void**)&ylo, g_ylo);
    cudaGetSymbolAddress((void**)&bqkv, g_bqkv);

    const int GEMM_SMEM = 3 * 32768;
    cudaFuncSetAttribute(tc_gemm, cudaFuncAttributeMaxDynamicSharedMemorySize,
                         GEMM_SMEM);
    const int ATTN_SMEM = 6 * 64 * 136 * 2;   // 104448
    cudaFuncSetAttribute(attn_mma, cudaFuncAttributeMaxDynamicSharedMemorySize,
                         ATTN_SMEM);

    // (1..3) prep needed by patch GEMM
    im2col_split<<<16384, 256>>>(x, phi, plo);
    split_elem<<<1024, 256>>>(conv_w, wchi, wclo);
    wtrans_all<<<dim3(32, 32, 4), dim3(32, 8)>>>(Wq, Wk, Wv, Wp, wthi, wtlo);
    // (4) tok = patches @ conv_w^T + conv_b   <-- ncu capture slot
    tc_gemm<<<dim3(8, 128), 256, GEMM_SMEM>>>(phi, plo, wchi, wclo, conv_b,
                                              nullptr, nullptr,
                                              tokhi, toklo, 16384, 1024, 256, 2);
    // (5) remaining prep
    bias_concat<<<12, 256>>>(bq, bk, bv, bqkv);
    // (6) fused qkv: q -> split bf16 (scaled), k/v -> fp32 present buffers
    tc_gemm<<<dim3(24, 128), 256, GEMM_SMEM>>>(tokhi, toklo, wthi, wtlo, bqkv,
                                               kout, vout, qhi, qlo,
                                               16384, 3072, 1024, 3);
    // (7) attention
    attn_mma<<<dim3(512, 4), 128, ATTN_SMEM>>>(qhi, qlo, kout, vout, yhi, ylo);
    // (8) y = yh @ Wp^T + bp
    tc_gemm<<<dim3(8, 128), 256, GEMM_SMEM>>>(yhi, ylo, wthi + 3 * 1048576,
                                              wtlo + 3 * 1048576, bp, out,
                                              nullptr, nullptr, nullptr,
                                              16384, 1024, 1024, 0);
}